// round 14
// baseline (speedup 1.0000x reference)
#include <cuda_runtime.h>
#include <cuda_bf16.h>
#include <stdint.h>
#include <math.h>

// ---------------- problem dims ----------------
#define Bq    4
#define NM    4
#define TT    1024
#define DD    256
#define DKc   16
#define DVc   64
#define DKPc  32
#define Hc    8
#define Ec    4
#define HEc   32
#define Rc    4
#define DAc   25
#define DPGc  316
#define DPGp  320
#define NDc   1024
#define DATTNc 512
#define BT    (Bq*TT)   // 4096

// ---------------- scratch (device globals) ----------------
__device__ __nv_bfloat16 g_xhat_h[(size_t)BT*NDc];
__device__ __nv_bfloat16 g_xhat_l[(size_t)BT*NDc];
__device__ int   g_qsel [Hc*BT];
__device__ int   g_kvsel[Hc*BT];
__device__ int   g_kvcnt[32];
__device__ int   g_qcnt [32];
__device__ int   g_idcnt[32];
__device__ int   g_kvlist[32*BT];
__device__ int   g_qlist [32*BT];
__device__ int   g_idlist[8*BT];
__device__ __nv_bfloat16 g_bfold_h[(size_t)HEc*NDc*64];
__device__ __nv_bfloat16 g_bfold_l[(size_t)HEc*NDc*64];
__device__ float g_dotkv[(size_t)Hc*BT*64];
__device__ float g_dotq [(size_t)Hc*BT*64];
__device__ __nv_bfloat16 g_hekv_h[(size_t)Hc*BT*DD];
__device__ __nv_bfloat16 g_hekv_l[(size_t)Hc*BT*DD];
__device__ __nv_bfloat16 g_heq_h [(size_t)Hc*BT*DD];
__device__ __nv_bfloat16 g_heq_l [(size_t)Hc*BT*DD];
__device__ __nv_bfloat16 g_pgmid_h[(size_t)Hc*BT*DPGp];
__device__ __nv_bfloat16 g_pgmid_l[(size_t)Hc*BT*DPGp];
__device__ __nv_bfloat16 g_Wpre_h[(size_t)HEc*DD*DATTNc];
__device__ __nv_bfloat16 g_Wpre_l[(size_t)HEc*DD*DATTNc];
__device__ __nv_bfloat16 g_Wpg1_h[(size_t)HEc*DD*DPGp];
__device__ __nv_bfloat16 g_Wpg1_l[(size_t)HEc*DD*DPGp];
__device__ __nv_bfloat16 g_Wpg2_h[(size_t)HEc*DPGp*DD];
__device__ __nv_bfloat16 g_Wpg2_l[(size_t)HEc*DPGp*DD];
__device__ __nv_bfloat16 g_Wvk_h[(size_t)Hc*DD*128];
__device__ __nv_bfloat16 g_Wvk_l[(size_t)Hc*DD*128];
__device__ __nv_bfloat16 g_Wmid_h[(size_t)HEc*DD*64];
__device__ __nv_bfloat16 g_Wmid_l[(size_t)HEc*DD*64];
__device__ float g_preh[(size_t)Hc*BT*DATTNc];
__device__ float g_posth[(size_t)Hc*BT*DD];
__device__ float g_vk  [(size_t)Hc*BT*128];
__device__ float g_mid [(size_t)Hc*BT*64];
__device__ float g_q [Hc*BT*DKPc];
__device__ float g_k [Hc*BT*DKPc];
__device__ float g_a [Hc*BT*DKPc];
__device__ float g_v [Hc*BT*DVc];
__device__ float g_be[Hc*BT];
__device__ float g_accres [BT*16];
__device__ float g_acchp  [BT*4];
__device__ float g_o  [Hc*BT*DVc];
__device__ float g_res[BT*DD];
__device__ float g_frq[16];
__device__ float g_shf[16];

// ---------------- helpers ----------------
__device__ __forceinline__ float sigmoidf_(float x){ return 1.f/(1.f+expf(-x)); }
__device__ __forceinline__ float siluf_(float x){ return x/(1.f+expf(-x)); }
__device__ __forceinline__ float softplusf_(float x){ return fmaxf(x,0.f)+log1pf(expf(-fabsf(x))); }

__device__ __forceinline__ float warpSum(float v){
    #pragma unroll
    for(int o=16;o;o>>=1) v += __shfl_xor_sync(0xffffffffu, v, o);
    return v;
}
__device__ __forceinline__ float blockSum256(float v, float* sred){
    int lane=threadIdx.x&31, wid=threadIdx.x>>5;
    v = warpSum(v);
    if(lane==0) sred[wid]=v;
    __syncthreads();
    if(wid==0){
        float x = (lane<8)? sred[lane] : 0.f;
        x = warpSum(x);
        if(lane==0) sred[0]=x;
    }
    __syncthreads();
    float r = sred[0];
    __syncthreads();
    return r;
}

template<int ACT> __device__ __forceinline__ float actf(float x){
    if(ACT==0) return siluf_(x)*0.125f;
    if(ACT==1) return siluf_(x);
    if(ACT==2) return sigmoidf_(x)*0.125f;
    return x;
}

// ---- tensor-core primitives (legacy mma path, bf16) ----
__device__ __forceinline__ void mma_bf16(float* c, const unsigned* a, const unsigned* b){
    asm volatile("mma.sync.aligned.m16n8k16.row.col.f32.bf16.bf16.f32 "
        "{%0,%1,%2,%3}, {%4,%5,%6,%7}, {%8,%9}, {%0,%1,%2,%3};\n"
        : "+f"(c[0]),"+f"(c[1]),"+f"(c[2]),"+f"(c[3])
        : "r"(a[0]),"r"(a[1]),"r"(a[2]),"r"(a[3]),"r"(b[0]),"r"(b[1]));
}
__device__ __forceinline__ void ldsm_x4(unsigned r[4], unsigned a){
    asm volatile("ldmatrix.sync.aligned.m8n8.x4.shared.b16 {%0,%1,%2,%3}, [%4];\n"
        : "=r"(r[0]),"=r"(r[1]),"=r"(r[2]),"=r"(r[3]) : "r"(a));
}
__device__ __forceinline__ void ldsm_x4t(unsigned r[4], unsigned a){
    asm volatile("ldmatrix.sync.aligned.m8n8.x4.trans.shared.b16 {%0,%1,%2,%3}, [%4];\n"
        : "=r"(r[0]),"=r"(r[1]),"=r"(r[2]),"=r"(r[3]) : "r"(a));
}
__device__ __forceinline__ void split_bf16(float v, __nv_bfloat16& h, __nv_bfloat16& l){
    h=__float2bfloat16(v);
    l=__float2bfloat16(v-__bfloat162float(h));
}
__device__ __forceinline__ void cpa16(unsigned s, const void* g){
    asm volatile("cp.async.cg.shared.global [%0], [%1], 16;\n" :: "r"(s), "l"(g));
}
__device__ __forceinline__ void cpa8(unsigned s, const void* g){
    asm volatile("cp.async.ca.shared.global [%0], [%1], 8;\n" :: "r"(s), "l"(g));
}
__device__ __forceinline__ void cpa_commit(){
    asm volatile("cp.async.commit_group;\n" ::: "memory");
}
__device__ __forceinline__ void cpa_wait1(){
    asm volatile("cp.async.wait_group 1;\n" ::: "memory");
}
__device__ __forceinline__ void cpa_wait0(){
    asm volatile("cp.async.wait_group 0;\n" ::: "memory");
}

// ---------------- kernel 1b: fold norm_w into phi tables + zero counters ----------------
__global__ void k_fold(const float* __restrict__ phi_pre, const float* __restrict__ phi_post,
                       const float* __restrict__ phi_res, const float* __restrict__ mhc_norm_w){
    if(blockIdx.x==0 && blockIdx.y==0){
        int tid=threadIdx.x;
        if(tid<32){ g_kvcnt[tid]=0; g_qcnt[tid]=0; }
        if(tid>=32 && tid<40) g_idcnt[tid-32]=BT;
        if(tid>=40 && tid<64) g_idcnt[tid-40+8]=0;
    }
    int g=blockIdx.y;
    int k=blockIdx.x*256+threadIdx.x;
    size_t gk=(size_t)g*NDc+k;
    float nw=mhc_norm_w[gk];
    float tmp[64];
    #pragma unroll
    for(int n=0;n<4;n++)  tmp[n]   = nw*phi_pre [gk*4+n];
    #pragma unroll
    for(int n=0;n<4;n++)  tmp[4+n] = nw*phi_post[gk*4+n];
    #pragma unroll
    for(int m=0;m<16;m++) tmp[8+m] = nw*phi_res [gk*16+m];
    #pragma unroll
    for(int n=24;n<64;n++) tmp[n]=0.f;
    __nv_bfloat16* oh=g_bfold_h + gk*64;
    __nv_bfloat16* ol=g_bfold_l + gk*64;
    #pragma unroll
    for(int n=0;n<64;n++){
        __nv_bfloat16 hb,lb; split_bf16(tmp[n],hb,lb);
        oh[n]=hb; ol[n]=lb;
    }
}

// ---------------- kernel 1: x_hat (split bf16) + routing fused ----------------
__global__ void k_prep(const float* __restrict__ stream, const float* __restrict__ pope_delta,
                       const float* __restrict__ q_router, const float* __restrict__ kv_router){
    int bt=blockIdx.x, tid=threadIdx.x;
    int b=bt>>10, t=bt&1023;
    int lane=tid&31, h=tid>>5;
    __shared__ float sred[8];
    __shared__ float r[DD];
    float v[NM]; float ss=0.f;
    #pragma unroll
    for(int n=0;n<NM;n++){
        v[n]=stream[(((b*NM+n)*TT)+t)*DD+tid];
        ss += v[n]*v[n];
    }
    float tot = blockSum256(ss, sred);
    float scale = rsqrtf(tot*(1.f/1024.f) + 1e-6f);
    #pragma unroll
    for(int n=0;n<NM;n++){
        float x=v[n]*scale;
        __nv_bfloat16 hb,lb; split_bf16(x,hb,lb);
        g_xhat_h[(size_t)bt*NDc + n*DD + tid]=hb;
        g_xhat_l[(size_t)bt*NDc + n*DD + tid]=lb;
    }
    r[tid] = (v[0]+v[1]+v[2]+v[3])*0.25f;
    if(tid<8) g_idlist[tid*BT+bt]=bt;
    if(bt==0 && tid<16){
        g_frq[tid] = (float)pow(10000.0, ((double)tid)/16.0);
        g_shf[tid] = 6.283185307179586f * sigmoidf_(pope_delta[tid]);
    }
    __syncthreads();

    float aq[4]={0,0,0,0}, ak[4]={0,0,0,0};
    for(int d=lane; d<DD; d+=32){
        float x=r[d];
        const float* wq=q_router + (h*DD+d)*Ec;
        const float* wk=kv_router+ (h*DD+d)*Ec;
        #pragma unroll
        for(int e=0;e<4;e++){ aq[e]+=x*wq[e]; ak[e]+=x*wk[e]; }
    }
    #pragma unroll
    for(int e=0;e<4;e++){ aq[e]=warpSum(aq[e]); ak[e]=warpSum(ak[e]); }
    if(lane==0){
        int bqi=0; float bv=fminf(fmaxf(aq[0],-10.f),10.f);
        #pragma unroll
        for(int e=1;e<4;e++){ float c=fminf(fmaxf(aq[e],-10.f),10.f); if(c>bv){bv=c;bqi=e;} }
        int bki=0; float kvb=fminf(fmaxf(ak[0],-10.f),10.f);
        #pragma unroll
        for(int e=1;e<4;e++){ float c=fminf(fmaxf(ak[e],-10.f),10.f); if(c>kvb){kvb=c;bki=e;} }
        g_qsel [h*BT+bt]=bqi;
        g_kvsel[h*BT+bt]=bki;
        int p=atomicAdd(&g_kvcnt[h*4+bki],1);
        g_kvlist[(h*4+bki)*BT+p]=bt;
        if(bqi!=0){
            int p2=atomicAdd(&g_qcnt[h*4+bqi],1);
            g_qlist[(h*4+bqi)*BT+p2]=bt;
        }
    }
}

// ---------------- kernel: split-convert weights (padded, zero-filled) ----------------
__global__ void k_cvtW(const float* __restrict__ W, __nv_bfloat16* __restrict__ Wh,
                       __nv_bfloat16* __restrict__ Wl, int Kr, int Nr, int Kp, int Np){
    int g=blockIdx.y;
    int idx=blockIdx.x*256+threadIdx.x;
    if(idx>=Kp*Np) return;
    int k=idx/Np, n=idx%Np;
    float v=(k<Kr && n<Nr)? W[((size_t)g*Kr+k)*Nr+n] : 0.f;
    __nv_bfloat16 hb,lb; split_bf16(v,hb,lb);
    Wh[((size_t)g*Kp+k)*Np+n]=hb;
    Wl[((size_t)g*Kp+k)*Np+n]=lb;
}

// ---------------- kernel: pack+split [Wv|Wk] per head -> [8][256][128] ----------------
__global__ void k_cvt_vk(const float* __restrict__ Wv, const float* __restrict__ Wk){
    int idx=blockIdx.x*256+threadIdx.x;
    if(idx>=Hc*DD*128) return;
    int h=idx/(DD*128), rem=idx%(DD*128);
    int k=rem/128, c=rem%128;
    float v=0.f;
    if(c<64)      v=Wv[((size_t)h*DD+k)*64+c];
    else if(c<80) v=Wk[((size_t)h*DD+k)*16+(c-64)];
    __nv_bfloat16 hb,lb; split_bf16(v,hb,lb);
    g_Wvk_h[idx]=hb; g_Wvk_l[idx]=lb;
}

// ---------------- kernel: pack+split [aup|bup|lAk|lAv] per expert -> [32][256][64] ----------------
__global__ void k_cvt_mid(const float* __restrict__ alpha_up, const float* __restrict__ beta_up,
                          const float* __restrict__ lora_A_k, const float* __restrict__ lora_A_v){
    int idx=blockIdx.x*256+threadIdx.x;
    if(idx>=HEc*DD*64) return;
    int g=idx/(DD*64), rem=idx%(DD*64);
    int k=rem/64, c=rem%64;
    float v=0.f;
    if(c<25)      v=alpha_up[((size_t)g*DD+k)*DAc+c];
    else if(c<50) v=beta_up [((size_t)g*DD+k)*DAc+(c-25)];
    else if(c<54) v=lora_A_k[((size_t)g*DD+k)*Rc +(c-50)];
    else if(c<58) v=lora_A_v[((size_t)g*DD+k)*Rc +(c-54)];
    __nv_bfloat16 hb,lb; split_bf16(v,hb,lb);
    g_Wmid_h[idx]=hb; g_Wmid_l[idx]=lb;
}

// ================= tensor-core grouped GEMM, pre-split, cp.async double-buffered =================
template<int KD,int ND,int ACT,int OUTSPLIT,int GDIV,int AHS,int DUAL>
__global__ void __launch_bounds__(256) k_gtmma2(
    const __nv_bfloat16* __restrict__ Ahg, const __nv_bfloat16* __restrict__ Alg,
    const __nv_bfloat16* __restrict__ Bhg, const __nv_bfloat16* __restrict__ Blg,
    float* __restrict__ Ob, __nv_bfloat16* __restrict__ Obh, __nv_bfloat16* __restrict__ Obl,
    const int* __restrict__ cnts, const int* __restrict__ lists,
    const int* __restrict__ cnts2, const int* __restrict__ lists2, float* __restrict__ Ob2)
{
    int g=blockIdx.z;
    const int* C=cnts; const int* L=lists; float* O=Ob;
    if(DUAL && g>=32){ g-=32; C=cnts2; L=lists2; O=Ob2; }
    int cnt=C[g];
    int m0=blockIdx.x*128;
    if(m0>=cnt) return;
    int h=g/GDIV;
    int n0=blockIdx.y*64;
    int tid=threadIdx.x, lane=tid&31, wid=tid>>5;
    int wm=wid&3, wn=wid>>2;

    __shared__ int stok[128];
    __shared__ __nv_bfloat16 Ah[2][128][24];
    __shared__ __nv_bfloat16 Al[2][128][24];
    __shared__ __nv_bfloat16 Bh[2][16][72];
    __shared__ __nv_bfloat16 Bl[2][16][72];

    if(tid<128){ int m=m0+tid; stok[tid]=(m<cnt)? L[g*BT+m] : -1; }
    __syncthreads();

    int arow=tid>>1, akoff=(tid&1)*8;
    int atok=stok[arow];
    const __nv_bfloat16* aH = Ahg + ((size_t)(AHS?h:0)*BT + (atok<0?0:atok))*KD;
    const __nv_bfloat16* aL = Alg + ((size_t)(AHS?h:0)*BT + (atok<0?0:atok))*KD;
    int bkr=tid>>4, bn=(tid&15)*4;
    const __nv_bfloat16* BH = Bhg + (size_t)g*KD*ND;
    const __nv_bfloat16* BL = Blg + (size_t)g*KD*ND;

    float acc[2][4][4];
    #pragma unroll
    for(int i=0;i<2;i++)
        #pragma unroll
        for(int j=0;j<4;j++){ acc[i][j][0]=0;acc[i][j][1]=0;acc[i][j][2]=0;acc[i][j][3]=0; }

    const unsigned APL=128*24*2u;
    const unsigned BPL=16*72*2u;
    unsigned sAh0=(unsigned)__cvta_generic_to_shared(&Ah[0][0][0]);
    unsigned sAl0=(unsigned)__cvta_generic_to_shared(&Al[0][0][0]);
    unsigned sBh0=(unsigned)__cvta_generic_to_shared(&Bh[0][0][0]);
    unsigned sBl0=(unsigned)__cvta_generic_to_shared(&Bl[0][0][0]);
    unsigned adst=(unsigned)(arow*24+akoff)*2u;
    unsigned bdst=(unsigned)(bkr*72+bn)*2u;
    unsigned aoff=((unsigned)((lane&15)*24 + (lane>>4)*8))*2u;
    unsigned boff=((unsigned)(((lane&7)+((lane>>3)&1)*8)*72 + (lane>>4)*8))*2u;

    const int NT=KD/16;
    cpa16(sAh0+adst, aH+akoff);
    cpa16(sAl0+adst, aL+akoff);
    cpa8 (sBh0+bdst, BH+(size_t)bkr*ND+n0+bn);
    cpa8 (sBl0+bdst, BL+(size_t)bkr*ND+n0+bn);
    cpa_commit();

    int buf=0;
    for(int t=0;t<NT;t++){
        if(t+1<NT){
            int kc=(t+1)*16;
            unsigned nb=buf^1;
            cpa16(sAh0+nb*APL+adst, aH+kc+akoff);
            cpa16(sAl0+nb*APL+adst, aL+kc+akoff);
            cpa8 (sBh0+nb*BPL+bdst, BH+(size_t)(kc+bkr)*ND+n0+bn);
            cpa8 (sBl0+nb*BPL+bdst, BL+(size_t)(kc+bkr)*ND+n0+bn);
            cpa_commit();
            cpa_wait1();
        } else {
            cpa_wait0();
        }
        __syncthreads();

        unsigned sAh=sAh0+buf*APL, sAl=sAl0+buf*APL;
        unsigned sBh=sBh0+buf*BPL, sBl=sBl0+buf*BPL;
        unsigned afh[2][4], afl[2][4], bfh[2][4], bfl[2][4];
        unsigned arow0 = (unsigned)(wm*32)*48u;
        ldsm_x4 (afh[0], sAh + arow0        + aoff);
        ldsm_x4 (afh[1], sAh + arow0 + 768u + aoff);
        ldsm_x4 (afl[0], sAl + arow0        + aoff);
        ldsm_x4 (afl[1], sAl + arow0 + 768u + aoff);
        unsigned bcol0 = (unsigned)(wn*32)*2u;
        ldsm_x4t(bfh[0], sBh + bcol0       + boff);
        ldsm_x4t(bfh[1], sBh + bcol0 + 32u + boff);
        ldsm_x4t(bfl[0], sBl + bcol0       + boff);
        ldsm_x4t(bfl[1], sBl + bcol0 + 32u + boff);

        #pragma unroll
        for(int m=0;m<2;m++){
            #pragma unroll
            for(int n=0;n<4;n++){
                unsigned bh2[2]={ bfh[n>>1][(n&1)*2], bfh[n>>1][(n&1)*2+1] };
                unsigned bl2[2]={ bfl[n>>1][(n&1)*2], bfl[n>>1][(n&1)*2+1] };
                mma_bf16(acc[m][n], afh[m], bh2);
                mma_bf16(acc[m][n], afh[m], bl2);
                mma_bf16(acc[m][n], afl[m], bh2);
            }
        }
        __syncthreads();
        buf^=1;
    }

    // ---- epilogue ----
    #pragma unroll
    for(int m=0;m<2;m++){
        int r0 = wm*32 + m*16 + (lane>>2);
        int tok0=stok[r0], tok1=stok[r0+8];
        #pragma unroll
        for(int n=0;n<4;n++){
            int col = n0 + wn*32 + n*8 + (lane&3)*2;
            if(OUTSPLIT){
                if(tok0>=0){
                    float x0=actf<ACT>(acc[m][n][0]), x1=actf<ACT>(acc[m][n][1]);
                    __nv_bfloat16 h0,l0,h1,l1; split_bf16(x0,h0,l0); split_bf16(x1,h1,l1);
                    *(__nv_bfloat162*)(Obh+((size_t)h*BT+tok0)*ND+col)=__halves2bfloat162(h0,h1);
                    *(__nv_bfloat162*)(Obl+((size_t)h*BT+tok0)*ND+col)=__halves2bfloat162(l0,l1);
                }
                if(tok1>=0){
                    float x0=actf<ACT>(acc[m][n][2]), x1=actf<ACT>(acc[m][n][3]);
                    __nv_bfloat16 h0,l0,h1,l1; split_bf16(x0,h0,l0); split_bf16(x1,h1,l1);
                    *(__nv_bfloat162*)(Obh+((size_t)h*BT+tok1)*ND+col)=__halves2bfloat162(h0,h1);
                    *(__nv_bfloat162*)(Obl+((size_t)h*BT+tok1)*ND+col)=__halves2bfloat162(l0,l1);
                }
            } else {
                if(col<ND){
                    if(tok0>=0){
                        float2 v; v.x=actf<ACT>(acc[m][n][0]); v.y=actf<ACT>(acc[m][n][1]);
                        *(float2*)(O + ((size_t)h*BT+tok0)*ND + col)=v;
                    }
                    if(tok1>=0){
                        float2 v; v.x=actf<ACT>(acc[m][n][2]); v.y=actf<ACT>(acc[m][n][3]);
                        *(float2*)(O + ((size_t)h*BT+tok1)*ND + col)=v;
                    }
                }
            }
        }
    }
}

// ---------------- kernel 3: per-token main, warp-per-head (conflict-free d mapping) ----------------
__global__ void __launch_bounds__(256) k_main(
    const float* __restrict__ stream,
    const float* __restrict__ Wq,
    const float* __restrict__ lora_A_q, const float* __restrict__ lora_B_q,
    const float* __restrict__ b_pre, const float* __restrict__ b_post, const float* __restrict__ b_res,
    const float* __restrict__ a_pre, const float* __restrict__ a_post, const float* __restrict__ a_res,
    const float* __restrict__ norm_w)
{
    int bt=blockIdx.x, tid=threadIdx.x;
    int b=bt>>10, t=bt&1023;
    int lane=tid&31, h=tid>>5;

    __shared__ float st[NM][DD];
    __shared__ float she[Hc][DD];
    __shared__ float sres_s[Hc][16];
    __shared__ float shp_s [Hc][4];

    #pragma unroll
    for(int n=0;n<NM;n++) st[n][tid]=stream[(((b*NM+n)*TT)+t)*DD+tid];
    __syncthreads();

    int eq  = g_qsel [h*BT+bt];
    int ekv = g_kvsel[h*BT+bt];
    int heq = h*Ec+eq, hekv = h*Ec+ekv;
    size_t row=(size_t)h*BT+bt;

    float dk = (lane<24)? g_dotkv[row*64+lane] : 0.f;

    float apk=a_pre[hekv], apo=a_post[hekv], ars=a_res[hekv];
    float hkv_l = sigmoidf_(apk*dk + b_pre[hekv*4+(lane&3)]);
    if(lane>=4 && lane<8) shp_s[h][lane-4] = 2.f*sigmoidf_(apo*dk + b_post[hekv*4+(lane-4)]);

    float dres = __shfl_sync(0xffffffffu, dk, (lane+8)&31);
    float M = (lane<16)? expf(ars*dres + b_res[hekv*16+lane]) : 0.f;
    #pragma unroll
    for(int it=0;it<6;it++){
        float rs = M + __shfl_xor_sync(0xffffffffu, M, 1);
        rs += __shfl_xor_sync(0xffffffffu, rs, 2);
        M /= rs;
        float cs = M + __shfl_xor_sync(0xffffffffu, M, 4);
        cs += __shfl_xor_sync(0xffffffffu, cs, 8);
        M /= cs;
    }
    if(lane<16) sres_s[h][lane]=M;

    float h0=__shfl_sync(0xffffffffu,hkv_l,0), h1=__shfl_sync(0xffffffffu,hkv_l,1);
    float h2=__shfl_sync(0xffffffffu,hkv_l,2), h3=__shfl_sync(0xffffffffu,hkv_l,3);
    // stride-32 d mapping: lane handles d = j*32 + lane (conflict-free smem)
    {
        float vv[8]; float ss=0.f;
        #pragma unroll
        for(int j=0;j<8;j++){
            int d=j*32+lane;
            float v=h0*st[0][d]+h1*st[1][d]+h2*st[2][d]+h3*st[3][d];
            vv[j]=v; ss+=v*v;
        }
        ss=warpSum(ss);
        float sc=rsqrtf(ss*(1.f/256.f)+1e-6f);
        #pragma unroll
        for(int j=0;j<8;j++){
            int d=j*32+lane;
            float ov=vv[j]*sc*norm_w[hekv*DD+d];
            __nv_bfloat16 hb,lb; split_bf16(ov, hb, lb);
            g_hekv_h[row*DD+d]=hb;
            g_hekv_l[row*DD+d]=lb;
        }
    }

    if(eq!=0){
        float apq=a_pre[heq];
        float dq = (lane<4)? g_dotq[row*64+lane] : 0.f;
        float hq_l = sigmoidf_(apq*dq + b_pre[heq*4+(lane&3)]);
        float q0=__shfl_sync(0xffffffffu,hq_l,0), q1=__shfl_sync(0xffffffffu,hq_l,1);
        float q2=__shfl_sync(0xffffffffu,hq_l,2), q3=__shfl_sync(0xffffffffu,hq_l,3);
        float vv[8]; float ss=0.f;
        #pragma unroll
        for(int j=0;j<8;j++){
            int d=j*32+lane;
            float v=q0*st[0][d]+q1*st[1][d]+q2*st[2][d]+q3*st[3][d];
            vv[j]=v; ss+=v*v;
        }
        ss=warpSum(ss);
        float sc=rsqrtf(ss*(1.f/256.f)+1e-6f);
        #pragma unroll
        for(int j=0;j<8;j++){
            int d=j*32+lane;
            float hv=vv[j]*sc*norm_w[heq*DD+d];
            she[h][d]=hv;
            __nv_bfloat16 hb,lb; split_bf16(hv, hb, lb);
            g_heq_h[row*DD+d]=hb;
            g_heq_l[row*DD+d]=lb;
        }
        __syncwarp();

        float s=0.f;
        if(lane<20){
            const float* wcol; int wstr;
            if(lane<16){ wcol = Wq + (size_t)h*DD*DKc + lane; wstr=DKc; }
            else       { wcol = lora_A_q + (size_t)heq*DD*Rc + (lane-16); wstr=Rc; }
            #pragma unroll 8
            for(int d=0;d<DD;d++) s += she[h][d]*wcol[d*wstr];
        }
        float slq_ = siluf_(s);
        float l0=__shfl_sync(0xffffffffu,slq_,16), l1=__shfl_sync(0xffffffffu,slq_,17);
        float l2=__shfl_sync(0xffffffffu,slq_,18), l3=__shfl_sync(0xffffffffu,slq_,19);
        float kv=0.f;
        if(lane<16){
            const float* w = lora_B_q + (size_t)heq*Rc*DKc + lane;
            kv = s + l0*w[0] + l1*w[DKc] + l2*w[2*DKc] + l3*w[3*DKc];
        }
        float ss2=kv*kv;
        #pragma unroll
        for(int o=8;o;o>>=1) ss2 += __shfl_xor_sync(0xffffffffu, ss2, o);
        if(lane<16){
            float nrm=sqrtf(ss2);
            float x=kv/fmaxf(nrm,1e-12f);
            float mu=softplusf_(x);
            float ph=(float)t*g_frq[lane];
            g_q[row*DKPc+lane]    = mu*cosf(ph);
            g_q[row*DKPc+16+lane] = mu*sinf(ph);
        }
    } else {
        g_q[row*DKPc + (lane&31)] = 0.f;
        #pragma unroll
        for(int j=0;j<8;j++) g_posth[row*DD+j*32+lane]=0.f;
    }

    __syncthreads();
    if(tid<16){
        float s=0.f;
        #pragma unroll
        for(int hh=0;hh<8;hh++) s+=sres_s[hh][tid];
        g_accres[bt*16+tid]=s;
    }
    if(tid>=32 && tid<36){
        int n=tid-32;
        float s=0.f;
        #pragma unroll
        for(int hh=0;hh<8;hh++) s+=shp_s[hh][n];
        g_acchp[bt*4+n]=s;
    }
}

// ---------------- kernel: finish kv path ----------------
__global__ void __launch_bounds__(64) k_finish(
    const float* __restrict__ alpha_down, const float* __restrict__ beta_down,
    const float* __restrict__ lora_B_k, const float* __restrict__ lora_B_v)
{
    int bt=blockIdx.x, h=blockIdx.y;
    int tid=threadIdx.x;
    int t=bt&1023;
    int ekv=g_kvsel[h*BT+bt];
    int g=h*4+ekv;
    __shared__ float mid[64];
    __shared__ float skv[16];
    size_t row=(size_t)h*BT+bt;
    mid[tid]=g_mid[row*64+tid];
    __syncthreads();

    {
        float s = g_vk[row*128+tid];
        const float* w = lora_B_v + (size_t)g*Rc*DVc + tid;
        #pragma unroll
        for(int r=0;r<Rc;r++) s += mid[54+r]*w[r*DVc];
        g_v[row*DVc+tid]=siluf_(s);
    }
    if(tid<32){
        const float* w = alpha_down + (size_t)g*DAc*DKPc + tid;
        float s=0.f;
        #pragma unroll
        for(int a=0;a<DAc;a++) s += mid[a]*w[a*DKPc];
        g_a[row*DKPc+tid]=sigmoidf_(s);
    } else if(tid==32){
        const float* w = beta_down + (size_t)g*DAc;
        float s=0.f;
        #pragma unroll
        for(int a=0;a<DAc;a++) s += mid[25+a]*w[a];
        g_be[row]=sigmoidf_(s);
    } else if(tid>=40 && tid<56){
        int k=tid-40;
        float s = g_vk[row*128+64+k];
        const float* w = lora_B_k + (size_t)g*Rc*DKc + k;
        #pragma unroll
        for(int r=0;r<Rc;r++) s += mid[50+r]*w[r*DKc];
        skv[k]=s;
    }
    __syncthreads();
    if(tid<32){
        float val=(tid<16)? skv[tid] : 0.f;
        float ss=val*val;
        #pragma unroll
        for(int o=8;o;o>>=1) ss += __shfl_xor_sync(0xffffffffu, ss, o);
        if(tid<16){
            float nrm=sqrtf(ss);
            float x=val/fmaxf(nrm,1e-12f);
            float mu=softplusf_(x);
            float ph=(float)t*g_frq[tid]-g_shf[tid];
            g_k[row*DKPc+tid]    = mu*cosf(ph);
            g_k[row*DKPc+16+tid] = mu*sinf(ph);
        }
    }
}

// ---------------- kernel: KDA recurrence ----------------
__global__ void __launch_bounds__(128) k_rec(){
    int hb = blockIdx.x;
    int warp = threadIdx.x>>5;
    int lane = threadIdx.x&31;
    int e = blockIdx.y*4 + warp;
    size_t b32=(size_t)hb*TT*DKPc, b64=(size_t)hb*TT*DVc, bb=(size_t)hb*TT;
    float S=0.f;
    float qc=g_q[b32+lane], kc=g_k[b32+lane], ac=g_a[b32+lane];
    float vc=g_v[b64+e], bec=g_be[bb];
    for(int t=0;t<TT;t++){
        float qn=0,kn=0,an=0,vn=0,ben=0;
        if(t+1<TT){
            size_t o32=b32+(size_t)(t+1)*DKPc;
            qn=g_q[o32+lane]; kn=g_k[o32+lane]; an=g_a[o32+lane];
            vn=g_v[b64+(size_t)(t+1)*DVc+e]; ben=g_be[bb+t+1];
        }
        float aS = ac*S;
        float p1 = kc*aS, p2=qc*aS, p3=qc*kc;
        #pragma unroll
        for(int o=16;o;o>>=1){
            p1 += __shfl_xor_sync(0xffffffffu,p1,o);
            p2 += __shfl_xor_sync(0xffffffffu,p2,o);
            p3 += __shfl_xor_sync(0xffffffffu,p3,o);
        }
        float w = bec*(vc-p1);
        S = aS + kc*w;
        float o_ = p2 + p3*w;
        if(lane==0) g_o[b64+(size_t)t*DVc+e]=o_;
        qc=qn;kc=kn;ac=an;vc=vn;bec=ben;
    }
}

// ---------------- kernel: result (32 tokens/block, chunked A) ----------------
__global__ void __launch_bounds__(256) k_result(const float* __restrict__ W_o){
    int bt0=blockIdx.x*32, tid=threadIdx.x;
    __shared__ float A[32][68];
    float out[32];
    #pragma unroll
    for(int r=0;r<32;r++) out[r]=0.f;

    for(int c0=0;c0<DATTNc;c0+=64){
        for(int idx=tid; idx<32*64; idx+=256){
            int r=idx>>6, cc=idx&63;
            int c=c0+cc;
            int bt=bt0+r;
            int hh=c>>6;
            float accp=0.f;
            #pragma unroll
            for(int h2=0;h2<8;h2++) accp += g_preh[((size_t)h2*BT+bt)*DATTNc + c];
            float ov = (g_qsel[hh*BT+bt]==0)? 0.f : g_o[((size_t)hh*BT+bt)*DVc + (c&63)];
            A[r][cc] = ov*(1.f/22.627416997969522f)*accp;
        }
        __syncthreads();
        for(int cc=0;cc<64;cc+=4){
            float w0=W_o[(size_t)(c0+cc)*DD+tid];
            float w1=W_o[(size_t)(c0+cc+1)*DD+tid];
            float w2=W_o[(size_t)(c0+cc+2)*DD+tid];
            float w3=W_o[(size_t)(c0+cc+3)*DD+tid];
            #pragma unroll
            for(int r=0;r<32;r++){
                float4 a=*(float4*)&A[r][cc];
                out[r]+=a.x*w0+a.y*w1+a.z*w2+a.w*w3;
            }
        }
        __syncthreads();
    }
    #pragma unroll
    for(int r=0;r<32;r++){
        int bt=bt0+r;
        float ap=0.f;
        #pragma unroll
        for(int h2=0;h2<8;h2++) ap += g_posth[((size_t)h2*BT+bt)*DD+tid];
        g_res[(size_t)bt*DD+tid]=out[r]*ap;
    }
}

// ---------------- kernel: final stream mixing ----------------
__global__ void k_final(const float* __restrict__ stream, float* __restrict__ out){
    int bt=blockIdx.x, tid=threadIdx.x;
    int b=bt>>10, t=bt&1023;
    __shared__ float sres[16], shp[4];
    if(tid<16) sres[tid]=g_accres[bt*16+tid]*0.125f;
    if(tid<4)  shp[tid] =g_acchp [bt*4+tid]*0.125f;
    __syncthreads();
    float r=g_res[(size_t)bt*DD+tid];
    float st[4];
    #pragma unroll
    for(int j=0;j<4;j++) st[j]=stream[(((b*NM+j)*TT)+t)*DD+tid];
    #pragma unroll
    for(int n=0;n<4;n++){
        float acc = sres[n*4+0]*st[0]+sres[n*4+1]*st[1]+sres[n*4+2]*st[2]+sres[n*4+3]*st[3];
        acc += shp[n]*r;
        out[(((b*NM+n)*TT)+t)*DD+tid]=acc;
    }
}

// ---------------- launch ----------------
extern "C" void kernel_launch(void* const* d_in, const int* in_sizes, int n_in,
                              void* d_out, int out_size){
    const float* stream     =(const float*)d_in[0];
    const float* Wq         =(const float*)d_in[1];
    const float* Wk         =(const float*)d_in[2];
    const float* Wv         =(const float*)d_in[3];
    const float* pope_delta =(const float*)d_in[4];
    const float* q_router   =(const float*)d_in[5];
    const float* kv_router  =(const float*)d_in[6];
    const float* lora_A_q   =(const float*)d_in[7];
    const float* lora_B_q   =(const float*)d_in[8];
    const float* lora_A_k   =(const float*)d_in[9];
    const float* lora_B_k   =(const float*)d_in[10];
    const float* lora_A_v   =(const float*)d_in[11];
    const float* lora_B_v   =(const float*)d_in[12];
    const float* alpha_up   =(const float*)d_in[13];
    const float* alpha_down =(const float*)d_in[14];
    const float* beta_up    =(const float*)d_in[15];
    const float* beta_down  =(const float*)d_in[16];
    const float* mhc_norm_w =(const float*)d_in[17];
    const float* phi_pre    =(const float*)d_in[18];
    const float* phi_post   =(const float*)d_in[19];
    const float* phi_res    =(const float*)d_in[20];
    const float* b_pre      =(const float*)d_in[21];
    const float* b_post     =(const float*)d_in[22];
    const float* b_res      =(const float*)d_in[23];
    const float* a_pre      =(const float*)d_in[24];
    const float* a_post     =(const float*)d_in[25];
    const float* a_res      =(const float*)d_in[26];
    const float* norm_w     =(const float*)d_in[27];
    const float* W_pre      =(const float*)d_in[28];
    const float* W_o        =(const float*)d_in[29];
    const float* W_pg1      =(const float*)d_in[30];
    const float* W_pg2      =(const float*)d_in[31];

    int* kvcnt_p; cudaGetSymbolAddress((void**)&kvcnt_p, g_kvcnt);
    int* qcnt_p;  cudaGetSymbolAddress((void**)&qcnt_p,  g_qcnt);
    int* idcnt_p; cudaGetSymbolAddress((void**)&idcnt_p, g_idcnt);
    int* kvlist_p;cudaGetSymbolAddress((void**)&kvlist_p,g_kvlist);
    int* qlist_p; cudaGetSymbolAddress((void**)&qlist_p, g_qlist);
    int* idlist_p;cudaGetSymbolAddress((void**)&idlist_p,g_idlist);
    float* preh_p; cudaGetSymbolAddress((void**)&preh_p, g_preh);
    float* posth_p;cudaGetSymbolAddress((void**)&posth_p,g_posth);
    float* dotkv_p;cudaGetSymbolAddress((void**)&dotkv_p,g_dotkv);
    float* dotq_p; cudaGetSymbolAddress((void**)&dotq_p, g_dotq);
    float* vk_p;   cudaGetSymbolAddress((void**)&vk_p,   g_vk);
    float* mid_p;  cudaGetSymbolAddress((void**)&mid_p,  g_mid);
    __nv_bfloat16 *xhath_p,*xhatl_p,*bfoldh_p,*bfoldl_p;
    __nv_bfloat16 *hekvh_p,*hekvl_p,*heqh_p,*heql_p,*pgmh_p,*pgml_p;
    __nv_bfloat16 *wpreh_p,*wprel_p,*wpg1h_p,*wpg1l_p,*wpg2h_p,*wpg2l_p;
    __nv_bfloat16 *wvkh_p,*wvkl_p,*wmidh_p,*wmidl_p;
    cudaGetSymbolAddress((void**)&xhath_p, g_xhat_h);
    cudaGetSymbolAddress((void**)&xhatl_p, g_xhat_l);
    cudaGetSymbolAddress((void**)&bfoldh_p,g_bfold_h);
    cudaGetSymbolAddress((void**)&bfoldl_p,g_bfold_l);
    cudaGetSymbolAddress((void**)&hekvh_p, g_hekv_h);
    cudaGetSymbolAddress((void**)&hekvl_p, g_hekv_l);
    cudaGetSymbolAddress((void**)&heqh_p,  g_heq_h);
    cudaGetSymbolAddress((void**)&heql_p,  g_heq_l);
    cudaGetSymbolAddress((void**)&pgmh_p,  g_pgmid_h);
    cudaGetSymbolAddress((void**)&pgml_p,  g_pgmid_l);
    cudaGetSymbolAddress((void**)&wpreh_p, g_Wpre_h);
    cudaGetSymbolAddress((void**)&wprel_p, g_Wpre_l);
    cudaGetSymbolAddress((void**)&wpg1h_p, g_Wpg1_h);
    cudaGetSymbolAddress((void**)&wpg1l_p, g_Wpg1_l);
    cudaGetSymbolAddress((void**)&wpg2h_p, g_Wpg2_h);
    cudaGetSymbolAddress((void**)&wpg2l_p, g_Wpg2_l);
    cudaGetSymbolAddress((void**)&wvkh_p,  g_Wvk_h);
    cudaGetSymbolAddress((void**)&wvkl_p,  g_Wvk_l);
    cudaGetSymbolAddress((void**)&wmidh_p, g_Wmid_h);
    cudaGetSymbolAddress((void**)&wmidl_p, g_Wmid_l);

    k_fold <<<dim3(4,32),256>>>(phi_pre, phi_post, phi_res, mhc_norm_w);
    k_prep <<<BT,256>>>(stream, pope_delta, q_router, kv_router);
    k_gtmma2<1024,64,3,0,4,0,1><<<dim3(32,1,64),256>>>(xhath_p, xhatl_p, bfoldh_p, bfoldl_p,
                                                       dotkv_p, (__nv_bfloat16*)0, (__nv_bfloat16*)0,
                                                       kvcnt_p, kvlist_p, qcnt_p, qlist_p, dotq_p);
    k_main <<<BT,256>>>(stream, Wq, lora_A_q, lora_B_q,
                        b_pre, b_post, b_res, a_pre, a_post, a_res, norm_w);
    k_cvtW<<<dim3((DD*DATTNc+255)/256,32),256>>>(W_pre, wpreh_p, wprel_p, DD, DATTNc, DD, DATTNc);
    k_cvtW<<<dim3((DD*DPGp+255)/256,32),256>>>(W_pg1, wpg1h_p, wpg1l_p, DD, DPGc, DD, DPGp);
    k_cvtW<<<dim3((DPGp*DD+255)/256,32),256>>>(W_pg2, wpg2h_p, wpg2l_p, DPGc, DD, DPGp, DD);
    k_cvt_vk <<<(Hc*DD*128+255)/256,256>>>(Wv, Wk);
    k_cvt_mid<<<(HEc*DD*64+255)/256,256>>>(alpha_up, beta_up, lora_A_k, lora_A_v);
    k_gtmma2<256,128,3,0,1,1,0><<<dim3(32,2,8),256>>>(hekvh_p, hekvl_p, wvkh_p, wvkl_p,
                                                      vk_p, (__nv_bfloat16*)0, (__nv_bfloat16*)0,
                                                      idcnt_p, idlist_p, (int*)0, (int*)0, (float*)0);
    k_gtmma2<256,512,0,0,4,1,0><<<dim3(32,8,32),256>>>(hekvh_p, hekvl_p, wpreh_p, wprel_p,
                                                       preh_p, (__nv_bfloat16*)0, (__nv_bfloat16*)0,
                                                       kvcnt_p, kvlist_p, (int*)0, (int*)0, (float*)0);
    k_gtmma2<256,64,1,0,4,1,0><<<dim3(32,1,32),256>>>(hekvh_p, hekvl_p, wmidh_p, wmidl_p,
                                                      mid_p, (__nv_bfloat16*)0, (__nv_bfloat16*)0,
                                                      kvcnt_p, kvlist_p, (int*)0, (int*)0, (float*)0);
    k_gtmma2<256,320,1,1,4,1,0><<<dim3(32,5,32),256>>>(heqh_p, heql_p, wpg1h_p, wpg1l_p,
                                                       (float*)0, pgmh_p, pgml_p,
                                                       qcnt_p, qlist_p, (int*)0, (int*)0, (float*)0);
    k_gtmma2<320,256,2,0,4,1,0><<<dim3(32,4,32),256>>>(pgmh_p, pgml_p, wpg2h_p, wpg2l_p,
                                                       posth_p, (__nv_bfloat16*)0, (__nv_bfloat16*)0,
                                                       qcnt_p, qlist_p, (int*)0, (int*)0, (float*)0);
    k_finish<<<dim3(BT,Hc),64>>>(alpha_down, beta_down, lora_B_k, lora_B_v);
    k_rec  <<<dim3(32,16),128>>>();
    k_result<<<128,256>>>(W_o);
    k_final <<<BT,256>>>(stream, (float*)d_out);
}

// round 15
// speedup vs baseline: 1.0555x; 1.0555x over previous
#include <cuda_runtime.h>
#include <cuda_bf16.h>
#include <stdint.h>
#include <math.h>

// ---------------- problem dims ----------------
#define Bq    4
#define NM    4
#define TT    1024
#define DD    256
#define DKc   16
#define DVc   64
#define DKPc  32
#define Hc    8
#define Ec    4
#define HEc   32
#define Rc    4
#define DAc   25
#define DPGc  316
#define DPGp  320
#define NDc   1024
#define DATTNc 512
#define BT    (Bq*TT)   // 4096

// ---------------- scratch (device globals) ----------------
__device__ __nv_bfloat16 g_xhat_h[(size_t)BT*NDc];
__device__ __nv_bfloat16 g_xhat_l[(size_t)BT*NDc];
__device__ float g_route[BT*DD];
__device__ int   g_qsel [Hc*BT];
__device__ int   g_kvsel[Hc*BT];
__device__ int   g_kvcnt[32];
__device__ int   g_qcnt [32];
__device__ int   g_idcnt[32];
__device__ int   g_kvlist[32*BT];
__device__ int   g_qlist [32*BT];
__device__ int   g_idlist[8*BT];
__device__ __nv_bfloat16 g_bfold_h[(size_t)HEc*NDc*64];
__device__ __nv_bfloat16 g_bfold_l[(size_t)HEc*NDc*64];
__device__ float g_dotkv[(size_t)Hc*BT*64];
__device__ float g_dotq [(size_t)Hc*BT*64];
__device__ __nv_bfloat16 g_hekv_h[(size_t)Hc*BT*DD];
__device__ __nv_bfloat16 g_hekv_l[(size_t)Hc*BT*DD];
__device__ __nv_bfloat16 g_heq_h [(size_t)Hc*BT*DD];
__device__ __nv_bfloat16 g_heq_l [(size_t)Hc*BT*DD];
__device__ __nv_bfloat16 g_pgmid_h[(size_t)Hc*BT*DPGp];
__device__ __nv_bfloat16 g_pgmid_l[(size_t)Hc*BT*DPGp];
__device__ __nv_bfloat16 g_Wpre_h[(size_t)HEc*DD*DATTNc];
__device__ __nv_bfloat16 g_Wpre_l[(size_t)HEc*DD*DATTNc];
__device__ __nv_bfloat16 g_Wpg1_h[(size_t)HEc*DD*DPGp];
__device__ __nv_bfloat16 g_Wpg1_l[(size_t)HEc*DD*DPGp];
__device__ __nv_bfloat16 g_Wpg2_h[(size_t)HEc*DPGp*DD];
__device__ __nv_bfloat16 g_Wpg2_l[(size_t)HEc*DPGp*DD];
__device__ __nv_bfloat16 g_Wvk_h[(size_t)Hc*DD*128];
__device__ __nv_bfloat16 g_Wvk_l[(size_t)Hc*DD*128];
__device__ __nv_bfloat16 g_Wmid_h[(size_t)HEc*DD*64];
__device__ __nv_bfloat16 g_Wmid_l[(size_t)HEc*DD*64];
__device__ float g_preh[(size_t)Hc*BT*DATTNc];
__device__ float g_posth[(size_t)Hc*BT*DD];
__device__ float g_vk  [(size_t)Hc*BT*128];
__device__ float g_mid [(size_t)Hc*BT*64];
__device__ float g_q [Hc*BT*DKPc];
__device__ float g_k [Hc*BT*DKPc];
__device__ float g_a [Hc*BT*DKPc];
__device__ float g_v [Hc*BT*DVc];
__device__ float g_be[Hc*BT];
__device__ float g_accres [BT*16];
__device__ float g_acchp  [BT*4];
__device__ float g_o  [Hc*BT*DVc];
__device__ float g_res[BT*DD];
__device__ float g_frq[16];
__device__ float g_shf[16];

// ---------------- helpers ----------------
__device__ __forceinline__ float sigmoidf_(float x){ return 1.f/(1.f+expf(-x)); }
__device__ __forceinline__ float siluf_(float x){ return x/(1.f+expf(-x)); }
__device__ __forceinline__ float softplusf_(float x){ return fmaxf(x,0.f)+log1pf(expf(-fabsf(x))); }

__device__ __forceinline__ float warpSum(float v){
    #pragma unroll
    for(int o=16;o;o>>=1) v += __shfl_xor_sync(0xffffffffu, v, o);
    return v;
}
__device__ __forceinline__ float blockSum256(float v, float* sred){
    int lane=threadIdx.x&31, wid=threadIdx.x>>5;
    v = warpSum(v);
    if(lane==0) sred[wid]=v;
    __syncthreads();
    if(wid==0){
        float x = (lane<8)? sred[lane] : 0.f;
        x = warpSum(x);
        if(lane==0) sred[0]=x;
    }
    __syncthreads();
    float r = sred[0];
    __syncthreads();
    return r;
}

template<int ACT> __device__ __forceinline__ float actf(float x){
    if(ACT==0) return siluf_(x)*0.125f;
    if(ACT==1) return siluf_(x);
    if(ACT==2) return sigmoidf_(x)*0.125f;
    return x;
}

// ---- tensor-core primitives (legacy mma path, bf16) ----
__device__ __forceinline__ void mma_bf16(float* c, const unsigned* a, const unsigned* b){
    asm volatile("mma.sync.aligned.m16n8k16.row.col.f32.bf16.bf16.f32 "
        "{%0,%1,%2,%3}, {%4,%5,%6,%7}, {%8,%9}, {%0,%1,%2,%3};\n"
        : "+f"(c[0]),"+f"(c[1]),"+f"(c[2]),"+f"(c[3])
        : "r"(a[0]),"r"(a[1]),"r"(a[2]),"r"(a[3]),"r"(b[0]),"r"(b[1]));
}
__device__ __forceinline__ void ldsm_x4(unsigned r[4], unsigned a){
    asm volatile("ldmatrix.sync.aligned.m8n8.x4.shared.b16 {%0,%1,%2,%3}, [%4];\n"
        : "=r"(r[0]),"=r"(r[1]),"=r"(r[2]),"=r"(r[3]) : "r"(a));
}
__device__ __forceinline__ void ldsm_x4t(unsigned r[4], unsigned a){
    asm volatile("ldmatrix.sync.aligned.m8n8.x4.trans.shared.b16 {%0,%1,%2,%3}, [%4];\n"
        : "=r"(r[0]),"=r"(r[1]),"=r"(r[2]),"=r"(r[3]) : "r"(a));
}
__device__ __forceinline__ void split_bf16(float v, __nv_bfloat16& h, __nv_bfloat16& l){
    h=__float2bfloat16(v);
    l=__float2bfloat16(v-__bfloat162float(h));
}
__device__ __forceinline__ void cpa16(unsigned s, const void* g){
    asm volatile("cp.async.cg.shared.global [%0], [%1], 16;\n" :: "r"(s), "l"(g));
}
__device__ __forceinline__ void cpa8(unsigned s, const void* g){
    asm volatile("cp.async.ca.shared.global [%0], [%1], 8;\n" :: "r"(s), "l"(g));
}
__device__ __forceinline__ void cpa_commit(){
    asm volatile("cp.async.commit_group;\n" ::: "memory");
}
__device__ __forceinline__ void cpa_wait1(){
    asm volatile("cp.async.wait_group 1;\n" ::: "memory");
}
__device__ __forceinline__ void cpa_wait0(){
    asm volatile("cp.async.wait_group 0;\n" ::: "memory");
}

// ---------------- kernel 1: x_hat (split bf16) + route_in + constants ----------------
__global__ void k_prep(const float* __restrict__ stream, const float* __restrict__ pope_delta){
    int bt=blockIdx.x, tid=threadIdx.x;
    int b=bt>>10, t=bt&1023;
    __shared__ float sred[8];
    float v[NM]; float ss=0.f;
    #pragma unroll
    for(int n=0;n<NM;n++){
        v[n]=stream[(((b*NM+n)*TT)+t)*DD+tid];
        ss += v[n]*v[n];
    }
    float tot = blockSum256(ss, sred);
    float scale = rsqrtf(tot*(1.f/1024.f) + 1e-6f);
    #pragma unroll
    for(int n=0;n<NM;n++){
        float x=v[n]*scale;
        __nv_bfloat16 hb,lb; split_bf16(x,hb,lb);
        g_xhat_h[(size_t)bt*NDc + n*DD + tid]=hb;
        g_xhat_l[(size_t)bt*NDc + n*DD + tid]=lb;
    }
    g_route[bt*DD+tid] = (v[0]+v[1]+v[2]+v[3])*0.25f;
    if(tid<8) g_idlist[tid*BT+bt]=bt;
    if(bt==0){
        if(tid<16){
            g_frq[tid] = (float)pow(10000.0, ((double)tid)/16.0);
            g_shf[tid] = 6.283185307179586f * sigmoidf_(pope_delta[tid]);
        }
        if(tid>=32 && tid<64){ g_kvcnt[tid-32]=0; g_qcnt[tid-32]=0; }
        if(tid>=64 && tid<72) g_idcnt[tid-64]=BT;
        if(tid>=72 && tid<96) g_idcnt[tid-72+8]=0;
    }
}

// ---------------- kernel: split-convert weights (padded, zero-filled) ----------------
__global__ void k_cvtW(const float* __restrict__ W, __nv_bfloat16* __restrict__ Wh,
                       __nv_bfloat16* __restrict__ Wl, int Kr, int Nr, int Kp, int Np){
    int g=blockIdx.y;
    int idx=blockIdx.x*256+threadIdx.x;
    if(idx>=Kp*Np) return;
    int k=idx/Np, n=idx%Np;
    float v=(k<Kr && n<Nr)? W[((size_t)g*Kr+k)*Nr+n] : 0.f;
    __nv_bfloat16 hb,lb; split_bf16(v,hb,lb);
    Wh[((size_t)g*Kp+k)*Np+n]=hb;
    Wl[((size_t)g*Kp+k)*Np+n]=lb;
}

// ---------------- kernel: pack+split [Wv|Wk] per head -> [8][256][128] ----------------
__global__ void k_cvt_vk(const float* __restrict__ Wv, const float* __restrict__ Wk){
    int idx=blockIdx.x*256+threadIdx.x;
    if(idx>=Hc*DD*128) return;
    int h=idx/(DD*128), rem=idx%(DD*128);
    int k=rem/128, c=rem%128;
    float v=0.f;
    if(c<64)      v=Wv[((size_t)h*DD+k)*64+c];
    else if(c<80) v=Wk[((size_t)h*DD+k)*16+(c-64)];
    __nv_bfloat16 hb,lb; split_bf16(v,hb,lb);
    g_Wvk_h[idx]=hb; g_Wvk_l[idx]=lb;
}

// ---------------- kernel: pack+split [aup|bup|lAk|lAv] per expert -> [32][256][64] ----------------
__global__ void k_cvt_mid(const float* __restrict__ alpha_up, const float* __restrict__ beta_up,
                          const float* __restrict__ lora_A_k, const float* __restrict__ lora_A_v){
    int idx=blockIdx.x*256+threadIdx.x;
    if(idx>=HEc*DD*64) return;
    int g=idx/(DD*64), rem=idx%(DD*64);
    int k=rem/64, c=rem%64;
    float v=0.f;
    if(c<25)      v=alpha_up[((size_t)g*DD+k)*DAc+c];
    else if(c<50) v=beta_up [((size_t)g*DD+k)*DAc+(c-25)];
    else if(c<54) v=lora_A_k[((size_t)g*DD+k)*Rc +(c-50)];
    else if(c<58) v=lora_A_v[((size_t)g*DD+k)*Rc +(c-54)];
    __nv_bfloat16 hb,lb; split_bf16(v,hb,lb);
    g_Wmid_h[idx]=hb; g_Wmid_l[idx]=lb;
}

// ---------------- kernel 1b: fold norm_w into phi tables (split, padded to 64) ----------------
__global__ void k_fold(const float* __restrict__ phi_pre, const float* __restrict__ phi_post,
                       const float* __restrict__ phi_res, const float* __restrict__ mhc_norm_w){
    int g=blockIdx.y;
    int k=blockIdx.x*256+threadIdx.x;
    size_t gk=(size_t)g*NDc+k;
    float nw=mhc_norm_w[gk];
    float tmp[64];
    #pragma unroll
    for(int n=0;n<4;n++)  tmp[n]   = nw*phi_pre [gk*4+n];
    #pragma unroll
    for(int n=0;n<4;n++)  tmp[4+n] = nw*phi_post[gk*4+n];
    #pragma unroll
    for(int m=0;m<16;m++) tmp[8+m] = nw*phi_res [gk*16+m];
    #pragma unroll
    for(int n=24;n<64;n++) tmp[n]=0.f;
    __nv_bfloat16* oh=g_bfold_h + gk*64;
    __nv_bfloat16* ol=g_bfold_l + gk*64;
    #pragma unroll
    for(int n=0;n<64;n++){
        __nv_bfloat16 hb,lb; split_bf16(tmp[n],hb,lb);
        oh[n]=hb; ol[n]=lb;
    }
}

// ---------------- kernel 2: routing + token lists ----------------
__global__ void k_route(const float* __restrict__ q_router, const float* __restrict__ kv_router){
    int bt=blockIdx.x; int tid=threadIdx.x; int lane=tid&31, h=tid>>5;
    __shared__ float r[DD];
    r[tid]=g_route[bt*DD+tid];
    __syncthreads();
    float aq[4]={0,0,0,0}, ak[4]={0,0,0,0};
    for(int d=lane; d<DD; d+=32){
        float x=r[d];
        const float* wq=q_router + (h*DD+d)*Ec;
        const float* wk=kv_router+ (h*DD+d)*Ec;
        #pragma unroll
        for(int e=0;e<4;e++){ aq[e]+=x*wq[e]; ak[e]+=x*wk[e]; }
    }
    #pragma unroll
    for(int e=0;e<4;e++){ aq[e]=warpSum(aq[e]); ak[e]=warpSum(ak[e]); }
    if(lane==0){
        int bqi=0; float bv=fminf(fmaxf(aq[0],-10.f),10.f);
        #pragma unroll
        for(int e=1;e<4;e++){ float c=fminf(fmaxf(aq[e],-10.f),10.f); if(c>bv){bv=c;bqi=e;} }
        int bki=0; float kvb=fminf(fmaxf(ak[0],-10.f),10.f);
        #pragma unroll
        for(int e=1;e<4;e++){ float c=fminf(fmaxf(ak[e],-10.f),10.f); if(c>kvb){kvb=c;bki=e;} }
        g_qsel [h*BT+bt]=bqi;
        g_kvsel[h*BT+bt]=bki;
        int p=atomicAdd(&g_kvcnt[h*4+bki],1);
        g_kvlist[(h*4+bki)*BT+p]=bt;
        if(bqi!=0){
            int p2=atomicAdd(&g_qcnt[h*4+bqi],1);
            g_qlist[(h*4+bqi)*BT+p2]=bt;
        }
    }
}

// ================= tensor-core grouped GEMM, pre-split, cp.async double-buffered =================
// GDIV: h = g/GDIV for output row base; AHS: A has per-h stride (1) or shared (0)
template<int KD,int ND,int ACT,int OUTSPLIT,int GDIV,int AHS>
__global__ void __launch_bounds__(256) k_gtmma2(
    const __nv_bfloat16* __restrict__ Ahg, const __nv_bfloat16* __restrict__ Alg,
    const __nv_bfloat16* __restrict__ Bhg, const __nv_bfloat16* __restrict__ Blg,
    float* __restrict__ Ob, __nv_bfloat16* __restrict__ Obh, __nv_bfloat16* __restrict__ Obl,
    const int* __restrict__ cnts, const int* __restrict__ lists)
{
    int g=blockIdx.z, cnt=cnts[g];
    int m0=blockIdx.x*128;
    if(m0>=cnt) return;
    int h=g/GDIV;
    int n0=blockIdx.y*64;
    int tid=threadIdx.x, lane=tid&31, wid=tid>>5;
    int wm=wid&3, wn=wid>>2;

    __shared__ int stok[128];
    __shared__ __nv_bfloat16 Ah[2][128][24];
    __shared__ __nv_bfloat16 Al[2][128][24];
    __shared__ __nv_bfloat16 Bh[2][16][72];
    __shared__ __nv_bfloat16 Bl[2][16][72];

    if(tid<128){ int m=m0+tid; stok[tid]=(m<cnt)? lists[g*BT+m] : -1; }
    __syncthreads();

    int arow=tid>>1, akoff=(tid&1)*8;
    int atok=stok[arow];
    const __nv_bfloat16* aH = Ahg + ((size_t)(AHS?h:0)*BT + (atok<0?0:atok))*KD;
    const __nv_bfloat16* aL = Alg + ((size_t)(AHS?h:0)*BT + (atok<0?0:atok))*KD;
    int bkr=tid>>4, bn=(tid&15)*4;
    const __nv_bfloat16* BH = Bhg + (size_t)g*KD*ND;
    const __nv_bfloat16* BL = Blg + (size_t)g*KD*ND;

    float acc[2][4][4];
    #pragma unroll
    for(int i=0;i<2;i++)
        #pragma unroll
        for(int j=0;j<4;j++){ acc[i][j][0]=0;acc[i][j][1]=0;acc[i][j][2]=0;acc[i][j][3]=0; }

    const unsigned APL=128*24*2u;
    const unsigned BPL=16*72*2u;
    unsigned sAh0=(unsigned)__cvta_generic_to_shared(&Ah[0][0][0]);
    unsigned sAl0=(unsigned)__cvta_generic_to_shared(&Al[0][0][0]);
    unsigned sBh0=(unsigned)__cvta_generic_to_shared(&Bh[0][0][0]);
    unsigned sBl0=(unsigned)__cvta_generic_to_shared(&Bl[0][0][0]);
    unsigned adst=(unsigned)(arow*24+akoff)*2u;
    unsigned bdst=(unsigned)(bkr*72+bn)*2u;
    unsigned aoff=((unsigned)((lane&15)*24 + (lane>>4)*8))*2u;
    unsigned boff=((unsigned)(((lane&7)+((lane>>3)&1)*8)*72 + (lane>>4)*8))*2u;

    const int NT=KD/16;
    cpa16(sAh0+adst, aH+akoff);
    cpa16(sAl0+adst, aL+akoff);
    cpa8 (sBh0+bdst, BH+(size_t)bkr*ND+n0+bn);
    cpa8 (sBl0+bdst, BL+(size_t)bkr*ND+n0+bn);
    cpa_commit();

    int buf=0;
    for(int t=0;t<NT;t++){
        if(t+1<NT){
            int kc=(t+1)*16;
            unsigned nb=buf^1;
            cpa16(sAh0+nb*APL+adst, aH+kc+akoff);
            cpa16(sAl0+nb*APL+adst, aL+kc+akoff);
            cpa8 (sBh0+nb*BPL+bdst, BH+(size_t)(kc+bkr)*ND+n0+bn);
            cpa8 (sBl0+nb*BPL+bdst, BL+(size_t)(kc+bkr)*ND+n0+bn);
            cpa_commit();
            cpa_wait1();
        } else {
            cpa_wait0();
        }
        __syncthreads();

        unsigned sAh=sAh0+buf*APL, sAl=sAl0+buf*APL;
        unsigned sBh=sBh0+buf*BPL, sBl=sBl0+buf*BPL;
        unsigned afh[2][4], afl[2][4], bfh[2][4], bfl[2][4];
        unsigned arow0 = (unsigned)(wm*32)*48u;
        ldsm_x4 (afh[0], sAh + arow0        + aoff);
        ldsm_x4 (afh[1], sAh + arow0 + 768u + aoff);
        ldsm_x4 (afl[0], sAl + arow0        + aoff);
        ldsm_x4 (afl[1], sAl + arow0 + 768u + aoff);
        unsigned bcol0 = (unsigned)(wn*32)*2u;
        ldsm_x4t(bfh[0], sBh + bcol0       + boff);
        ldsm_x4t(bfh[1], sBh + bcol0 + 32u + boff);
        ldsm_x4t(bfl[0], sBl + bcol0       + boff);
        ldsm_x4t(bfl[1], sBl + bcol0 + 32u + boff);

        #pragma unroll
        for(int m=0;m<2;m++){
            #pragma unroll
            for(int n=0;n<4;n++){
                unsigned bh2[2]={ bfh[n>>1][(n&1)*2], bfh[n>>1][(n&1)*2+1] };
                unsigned bl2[2]={ bfl[n>>1][(n&1)*2], bfl[n>>1][(n&1)*2+1] };
                mma_bf16(acc[m][n], afh[m], bh2);
                mma_bf16(acc[m][n], afh[m], bl2);
                mma_bf16(acc[m][n], afl[m], bh2);
            }
        }
        __syncthreads();
        buf^=1;
    }

    // ---- epilogue ----
    #pragma unroll
    for(int m=0;m<2;m++){
        int r0 = wm*32 + m*16 + (lane>>2);
        int tok0=stok[r0], tok1=stok[r0+8];
        #pragma unroll
        for(int n=0;n<4;n++){
            int col = n0 + wn*32 + n*8 + (lane&3)*2;
            if(OUTSPLIT){
                if(tok0>=0){
                    float x0=actf<ACT>(acc[m][n][0]), x1=actf<ACT>(acc[m][n][1]);
                    __nv_bfloat16 h0,l0,h1,l1; split_bf16(x0,h0,l0); split_bf16(x1,h1,l1);
                    *(__nv_bfloat162*)(Obh+((size_t)h*BT+tok0)*ND+col)=__halves2bfloat162(h0,h1);
                    *(__nv_bfloat162*)(Obl+((size_t)h*BT+tok0)*ND+col)=__halves2bfloat162(l0,l1);
                }
                if(tok1>=0){
                    float x0=actf<ACT>(acc[m][n][2]), x1=actf<ACT>(acc[m][n][3]);
                    __nv_bfloat16 h0,l0,h1,l1; split_bf16(x0,h0,l0); split_bf16(x1,h1,l1);
                    *(__nv_bfloat162*)(Obh+((size_t)h*BT+tok1)*ND+col)=__halves2bfloat162(h0,h1);
                    *(__nv_bfloat162*)(Obl+((size_t)h*BT+tok1)*ND+col)=__halves2bfloat162(l0,l1);
                }
            } else {
                if(col<ND){
                    if(tok0>=0){
                        float2 v; v.x=actf<ACT>(acc[m][n][0]); v.y=actf<ACT>(acc[m][n][1]);
                        *(float2*)(Ob + ((size_t)h*BT+tok0)*ND + col)=v;
                    }
                    if(tok1>=0){
                        float2 v; v.x=actf<ACT>(acc[m][n][2]); v.y=actf<ACT>(acc[m][n][3]);
                        *(float2*)(Ob + ((size_t)h*BT+tok1)*ND + col)=v;
                    }
                }
            }
        }
    }
}

// ---------------- kernel 3: per-token main, warp-per-head (conflict-free d mapping) ----------------
__global__ void __launch_bounds__(256) k_main(
    const float* __restrict__ stream,
    const float* __restrict__ Wq,
    const float* __restrict__ lora_A_q, const float* __restrict__ lora_B_q,
    const float* __restrict__ b_pre, const float* __restrict__ b_post, const float* __restrict__ b_res,
    const float* __restrict__ a_pre, const float* __restrict__ a_post, const float* __restrict__ a_res,
    const float* __restrict__ norm_w)
{
    int bt=blockIdx.x, tid=threadIdx.x;
    int b=bt>>10, t=bt&1023;
    int lane=tid&31, h=tid>>5;

    __shared__ float st[NM][DD];
    __shared__ float she[Hc][DD];
    __shared__ float sres_s[Hc][16];
    __shared__ float shp_s [Hc][4];

    #pragma unroll
    for(int n=0;n<NM;n++) st[n][tid]=stream[(((b*NM+n)*TT)+t)*DD+tid];
    __syncthreads();

    int eq  = g_qsel [h*BT+bt];
    int ekv = g_kvsel[h*BT+bt];
    int heq = h*Ec+eq, hekv = h*Ec+ekv;
    size_t row=(size_t)h*BT+bt;

    float dk = (lane<24)? g_dotkv[row*64+lane] : 0.f;

    float apk=a_pre[hekv], apo=a_post[hekv], ars=a_res[hekv];
    float hkv_l = sigmoidf_(apk*dk + b_pre[hekv*4+(lane&3)]);
    if(lane>=4 && lane<8) shp_s[h][lane-4] = 2.f*sigmoidf_(apo*dk + b_post[hekv*4+(lane-4)]);

    float dres = __shfl_sync(0xffffffffu, dk, (lane+8)&31);
    float M = (lane<16)? expf(ars*dres + b_res[hekv*16+lane]) : 0.f;
    #pragma unroll
    for(int it=0;it<6;it++){
        float rs = M + __shfl_xor_sync(0xffffffffu, M, 1);
        rs += __shfl_xor_sync(0xffffffffu, rs, 2);
        M /= rs;
        float cs = M + __shfl_xor_sync(0xffffffffu, M, 4);
        cs += __shfl_xor_sync(0xffffffffu, cs, 8);
        M /= cs;
    }
    if(lane<16) sres_s[h][lane]=M;

    float h0=__shfl_sync(0xffffffffu,hkv_l,0), h1=__shfl_sync(0xffffffffu,hkv_l,1);
    float h2=__shfl_sync(0xffffffffu,hkv_l,2), h3=__shfl_sync(0xffffffffu,hkv_l,3);
    // stride-32 d mapping: lane handles d = j*32 + lane (conflict-free smem)
    {
        float vv[8]; float ss=0.f;
        #pragma unroll
        for(int j=0;j<8;j++){
            int d=j*32+lane;
            float v=h0*st[0][d]+h1*st[1][d]+h2*st[2][d]+h3*st[3][d];
            vv[j]=v; ss+=v*v;
        }
        ss=warpSum(ss);
        float sc=rsqrtf(ss*(1.f/256.f)+1e-6f);
        #pragma unroll
        for(int j=0;j<8;j++){
            int d=j*32+lane;
            float ov=vv[j]*sc*norm_w[hekv*DD+d];
            __nv_bfloat16 hb,lb; split_bf16(ov, hb, lb);
            g_hekv_h[row*DD+d]=hb;
            g_hekv_l[row*DD+d]=lb;
        }
    }

    if(eq!=0){
        float apq=a_pre[heq];
        float dq = (lane<4)? g_dotq[row*64+lane] : 0.f;
        float hq_l = sigmoidf_(apq*dq + b_pre[heq*4+(lane&3)]);
        float q0=__shfl_sync(0xffffffffu,hq_l,0), q1=__shfl_sync(0xffffffffu,hq_l,1);
        float q2=__shfl_sync(0xffffffffu,hq_l,2), q3=__shfl_sync(0xffffffffu,hq_l,3);
        float vv[8]; float ss=0.f;
        #pragma unroll
        for(int j=0;j<8;j++){
            int d=j*32+lane;
            float v=q0*st[0][d]+q1*st[1][d]+q2*st[2][d]+q3*st[3][d];
            vv[j]=v; ss+=v*v;
        }
        ss=warpSum(ss);
        float sc=rsqrtf(ss*(1.f/256.f)+1e-6f);
        #pragma unroll
        for(int j=0;j<8;j++){
            int d=j*32+lane;
            float hv=vv[j]*sc*norm_w[heq*DD+d];
            she[h][d]=hv;
            __nv_bfloat16 hb,lb; split_bf16(hv, hb, lb);
            g_heq_h[row*DD+d]=hb;
            g_heq_l[row*DD+d]=lb;
        }
        __syncwarp();

        float s=0.f;
        if(lane<20){
            const float* wcol; int wstr;
            if(lane<16){ wcol = Wq + (size_t)h*DD*DKc + lane; wstr=DKc; }
            else       { wcol = lora_A_q + (size_t)heq*DD*Rc + (lane-16); wstr=Rc; }
            #pragma unroll 8
            for(int d=0;d<DD;d++) s += she[h][d]*wcol[d*wstr];
        }
        float slq_ = siluf_(s);
        float l0=__shfl_sync(0xffffffffu,slq_,16), l1=__shfl_sync(0xffffffffu,slq_,17);
        float l2=__shfl_sync(0xffffffffu,slq_,18), l3=__shfl_sync(0xffffffffu,slq_,19);
        float kv=0.f;
        if(lane<16){
            const float* w = lora_B_q + (size_t)heq*Rc*DKc + lane;
            kv = s + l0*w[0] + l1*w[DKc] + l2*w[2*DKc] + l3*w[3*DKc];
        }
        float ss2=kv*kv;
        #pragma unroll
        for(int o=8;o;o>>=1) ss2 += __shfl_xor_sync(0xffffffffu, ss2, o);
        if(lane<16){
            float nrm=sqrtf(ss2);
            float x=kv/fmaxf(nrm,1e-12f);
            float mu=softplusf_(x);
            float ph=(float)t*g_frq[lane];
            g_q[row*DKPc+lane]    = mu*cosf(ph);
            g_q[row*DKPc+16+lane] = mu*sinf(ph);
        }
    } else {
        g_q[row*DKPc + (lane&31)] = 0.f;
        #pragma unroll
        for(int j=0;j<8;j++) g_posth[row*DD+j*32+lane]=0.f;
    }

    __syncthreads();
    if(tid<16){
        float s=0.f;
        #pragma unroll
        for(int hh=0;hh<8;hh++) s+=sres_s[hh][tid];
        g_accres[bt*16+tid]=s;
    }
    if(tid>=32 && tid<36){
        int n=tid-32;
        float s=0.f;
        #pragma unroll
        for(int hh=0;hh<8;hh++) s+=shp_s[hh][n];
        g_acchp[bt*4+n]=s;
    }
}

// ---------------- kernel: finish kv path ----------------
__global__ void __launch_bounds__(64) k_finish(
    const float* __restrict__ alpha_down, const float* __restrict__ beta_down,
    const float* __restrict__ lora_B_k, const float* __restrict__ lora_B_v)
{
    int bt=blockIdx.x, h=blockIdx.y;
    int tid=threadIdx.x;
    int t=bt&1023;
    int ekv=g_kvsel[h*BT+bt];
    int g=h*4+ekv;
    __shared__ float mid[64];
    __shared__ float skv[16];
    size_t row=(size_t)h*BT+bt;
    mid[tid]=g_mid[row*64+tid];
    __syncthreads();

    {
        float s = g_vk[row*128+tid];
        const float* w = lora_B_v + (size_t)g*Rc*DVc + tid;
        #pragma unroll
        for(int r=0;r<Rc;r++) s += mid[54+r]*w[r*DVc];
        g_v[row*DVc+tid]=siluf_(s);
    }
    if(tid<32){
        const float* w = alpha_down + (size_t)g*DAc*DKPc + tid;
        float s=0.f;
        #pragma unroll
        for(int a=0;a<DAc;a++) s += mid[a]*w[a*DKPc];
        g_a[row*DKPc+tid]=sigmoidf_(s);
    } else if(tid==32){
        const float* w = beta_down + (size_t)g*DAc;
        float s=0.f;
        #pragma unroll
        for(int a=0;a<DAc;a++) s += mid[25+a]*w[a];
        g_be[row]=sigmoidf_(s);
    } else if(tid>=40 && tid<56){
        int k=tid-40;
        float s = g_vk[row*128+64+k];
        const float* w = lora_B_k + (size_t)g*Rc*DKc + k;
        #pragma unroll
        for(int r=0;r<Rc;r++) s += mid[50+r]*w[r*DKc];
        skv[k]=s;
    }
    __syncthreads();
    if(tid<32){
        float val=(tid<16)? skv[tid] : 0.f;
        float ss=val*val;
        #pragma unroll
        for(int o=8;o;o>>=1) ss += __shfl_xor_sync(0xffffffffu, ss, o);
        if(tid<16){
            float nrm=sqrtf(ss);
            float x=val/fmaxf(nrm,1e-12f);
            float mu=softplusf_(x);
            float ph=(float)t*g_frq[tid]-g_shf[tid];
            g_k[row*DKPc+tid]    = mu*cosf(ph);
            g_k[row*DKPc+16+tid] = mu*sinf(ph);
        }
    }
}

// ---------------- kernel: KDA recurrence ----------------
__global__ void __launch_bounds__(128) k_rec(){
    int hb = blockIdx.x;
    int warp = threadIdx.x>>5;
    int lane = threadIdx.x&31;
    int e = blockIdx.y*4 + warp;
    size_t b32=(size_t)hb*TT*DKPc, b64=(size_t)hb*TT*DVc, bb=(size_t)hb*TT;
    float S=0.f;
    float qc=g_q[b32+lane], kc=g_k[b32+lane], ac=g_a[b32+lane];
    float vc=g_v[b64+e], bec=g_be[bb];
    for(int t=0;t<TT;t++){
        float qn=0,kn=0,an=0,vn=0,ben=0;
        if(t+1<TT){
            size_t o32=b32+(size_t)(t+1)*DKPc;
            qn=g_q[o32+lane]; kn=g_k[o32+lane]; an=g_a[o32+lane];
            vn=g_v[b64+(size_t)(t+1)*DVc+e]; ben=g_be[bb+t+1];
        }
        float aS = ac*S;
        float p1 = kc*aS, p2=qc*aS, p3=qc*kc;
        #pragma unroll
        for(int o=16;o;o>>=1){
            p1 += __shfl_xor_sync(0xffffffffu,p1,o);
            p2 += __shfl_xor_sync(0xffffffffu,p2,o);
            p3 += __shfl_xor_sync(0xffffffffu,p3,o);
        }
        float w = bec*(vc-p1);
        S = aS + kc*w;
        float o_ = p2 + p3*w;
        if(lane==0) g_o[b64+(size_t)t*DVc+e]=o_;
        qc=qn;kc=kn;ac=an;vc=vn;bec=ben;
    }
}

// ---------------- kernel: result (16 tokens/block) ----------------
__global__ void __launch_bounds__(256) k_result(const float* __restrict__ W_o){
    int bt0=blockIdx.x*16, tid=threadIdx.x;
    __shared__ float A[16][512];
    for(int idx=tid; idx<16*512; idx+=256){
        int r=idx>>9, c=idx&511;
        int bt=bt0+r;
        int hh=c>>6;
        float accp=0.f;
        #pragma unroll
        for(int h2=0;h2<8;h2++) accp += g_preh[((size_t)h2*BT+bt)*DATTNc + c];
        float ov = (g_qsel[hh*BT+bt]==0)? 0.f : g_o[((size_t)hh*BT+bt)*DVc + (c&63)];
        A[r][c] = ov*(1.f/22.627416997969522f)*accp;
    }
    __syncthreads();
    float out[16];
    #pragma unroll
    for(int r=0;r<16;r++) out[r]=0.f;
    for(int c=0;c<512;c+=4){
        float w0=W_o[(size_t)c*DD+tid];
        float w1=W_o[(size_t)(c+1)*DD+tid];
        float w2=W_o[(size_t)(c+2)*DD+tid];
        float w3=W_o[(size_t)(c+3)*DD+tid];
        #pragma unroll
        for(int r=0;r<16;r++){
            float4 a=*(float4*)&A[r][c];
            out[r]+=a.x*w0+a.y*w1+a.z*w2+a.w*w3;
        }
    }
    #pragma unroll
    for(int r=0;r<16;r++){
        int bt=bt0+r;
        float ap=0.f;
        #pragma unroll
        for(int h2=0;h2<8;h2++) ap += g_posth[((size_t)h2*BT+bt)*DD+tid];
        g_res[(size_t)bt*DD+tid]=out[r]*ap;
    }
}

// ---------------- kernel: final stream mixing ----------------
__global__ void k_final(const float* __restrict__ stream, float* __restrict__ out){
    int bt=blockIdx.x, tid=threadIdx.x;
    int b=bt>>10, t=bt&1023;
    __shared__ float sres[16], shp[4];
    if(tid<16) sres[tid]=g_accres[bt*16+tid]*0.125f;
    if(tid<4)  shp[tid] =g_acchp [bt*4+tid]*0.125f;
    __syncthreads();
    float r=g_res[(size_t)bt*DD+tid];
    float st[4];
    #pragma unroll
    for(int j=0;j<4;j++) st[j]=stream[(((b*NM+j)*TT)+t)*DD+tid];
    #pragma unroll
    for(int n=0;n<4;n++){
        float acc = sres[n*4+0]*st[0]+sres[n*4+1]*st[1]+sres[n*4+2]*st[2]+sres[n*4+3]*st[3];
        acc += shp[n]*r;
        out[(((b*NM+n)*TT)+t)*DD+tid]=acc;
    }
}

// ---------------- launch ----------------
extern "C" void kernel_launch(void* const* d_in, const int* in_sizes, int n_in,
                              void* d_out, int out_size){
    const float* stream     =(const float*)d_in[0];
    const float* Wq         =(const float*)d_in[1];
    const float* Wk         =(const float*)d_in[2];
    const float* Wv         =(const float*)d_in[3];
    const float* pope_delta =(const float*)d_in[4];
    const float* q_router   =(const float*)d_in[5];
    const float* kv_router  =(const float*)d_in[6];
    const float* lora_A_q   =(const float*)d_in[7];
    const float* lora_B_q   =(const float*)d_in[8];
    const float* lora_A_k   =(const float*)d_in[9];
    const float* lora_B_k   =(const float*)d_in[10];
    const float* lora_A_v   =(const float*)d_in[11];
    const float* lora_B_v   =(const float*)d_in[12];
    const float* alpha_up   =(const float*)d_in[13];
    const float* alpha_down =(const float*)d_in[14];
    const float* beta_up    =(const float*)d_in[15];
    const float* beta_down  =(const float*)d_in[16];
    const float* mhc_norm_w =(const float*)d_in[17];
    const float* phi_pre    =(const float*)d_in[18];
    const float* phi_post   =(const float*)d_in[19];
    const float* phi_res    =(const float*)d_in[20];
    const float* b_pre      =(const float*)d_in[21];
    const float* b_post     =(const float*)d_in[22];
    const float* b_res      =(const float*)d_in[23];
    const float* a_pre      =(const float*)d_in[24];
    const float* a_post     =(const float*)d_in[25];
    const float* a_res      =(const float*)d_in[26];
    const float* norm_w     =(const float*)d_in[27];
    const float* W_pre      =(const float*)d_in[28];
    const float* W_o        =(const float*)d_in[29];
    const float* W_pg1      =(const float*)d_in[30];
    const float* W_pg2      =(const float*)d_in[31];

    int* kvcnt_p; cudaGetSymbolAddress((void**)&kvcnt_p, g_kvcnt);
    int* qcnt_p;  cudaGetSymbolAddress((void**)&qcnt_p,  g_qcnt);
    int* idcnt_p; cudaGetSymbolAddress((void**)&idcnt_p, g_idcnt);
    int* kvlist_p;cudaGetSymbolAddress((void**)&kvlist_p,g_kvlist);
    int* qlist_p; cudaGetSymbolAddress((void**)&qlist_p, g_qlist);
    int* idlist_p;cudaGetSymbolAddress((void**)&idlist_p,g_idlist);
    float* preh_p; cudaGetSymbolAddress((void**)&preh_p, g_preh);
    float* posth_p;cudaGetSymbolAddress((void**)&posth_p,g_posth);
    float* dotkv_p;cudaGetSymbolAddress((void**)&dotkv_p,g_dotkv);
    float* dotq_p; cudaGetSymbolAddress((void**)&dotq_p, g_dotq);
    float* vk_p;   cudaGetSymbolAddress((void**)&vk_p,   g_vk);
    float* mid_p;  cudaGetSymbolAddress((void**)&mid_p,  g_mid);
    __nv_bfloat16 *xhath_p,*xhatl_p,*bfoldh_p,*bfoldl_p;
    __nv_bfloat16 *hekvh_p,*hekvl_p,*heqh_p,*heql_p,*pgmh_p,*pgml_p;
    __nv_bfloat16 *wpreh_p,*wprel_p,*wpg1h_p,*wpg1l_p,*wpg2h_p,*wpg2l_p;
    __nv_bfloat16 *wvkh_p,*wvkl_p,*wmidh_p,*wmidl_p;
    cudaGetSymbolAddress((void**)&xhath_p, g_xhat_h);
    cudaGetSymbolAddress((void**)&xhatl_p, g_xhat_l);
    cudaGetSymbolAddress((void**)&bfoldh_p,g_bfold_h);
    cudaGetSymbolAddress((void**)&bfoldl_p,g_bfold_l);
    cudaGetSymbolAddress((void**)&hekvh_p, g_hekv_h);
    cudaGetSymbolAddress((void**)&hekvl_p, g_hekv_l);
    cudaGetSymbolAddress((void**)&heqh_p,  g_heq_h);
    cudaGetSymbolAddress((void**)&heql_p,  g_heq_l);
    cudaGetSymbolAddress((void**)&pgmh_p,  g_pgmid_h);
    cudaGetSymbolAddress((void**)&pgml_p,  g_pgmid_l);
    cudaGetSymbolAddress((void**)&wpreh_p, g_Wpre_h);
    cudaGetSymbolAddress((void**)&wprel_p, g_Wpre_l);
    cudaGetSymbolAddress((void**)&wpg1h_p, g_Wpg1_h);
    cudaGetSymbolAddress((void**)&wpg1l_p, g_Wpg1_l);
    cudaGetSymbolAddress((void**)&wpg2h_p, g_Wpg2_h);
    cudaGetSymbolAddress((void**)&wpg2l_p, g_Wpg2_l);
    cudaGetSymbolAddress((void**)&wvkh_p,  g_Wvk_h);
    cudaGetSymbolAddress((void**)&wvkl_p,  g_Wvk_l);
    cudaGetSymbolAddress((void**)&wmidh_p, g_Wmid_h);
    cudaGetSymbolAddress((void**)&wmidl_p, g_Wmid_l);

    k_prep <<<BT,256>>>(stream, pope_delta);
    k_fold <<<dim3(4,32),256>>>(phi_pre, phi_post, phi_res, mhc_norm_w);
    k_route<<<BT,256>>>(q_router, kv_router);
    k_gtmma2<1024,64,3,0,4,0><<<dim3(32,1,32),256>>>(xhath_p, xhatl_p, bfoldh_p, bfoldl_p,
                                                     dotkv_p, (__nv_bfloat16*)0, (__nv_bfloat16*)0,
                                                     kvcnt_p, kvlist_p);
    k_gtmma2<1024,64,3,0,4,0><<<dim3(32,1,32),256>>>(xhath_p, xhatl_p, bfoldh_p, bfoldl_p,
                                                     dotq_p, (__nv_bfloat16*)0, (__nv_bfloat16*)0,
                                                     qcnt_p, qlist_p);
    k_main <<<BT,256>>>(stream, Wq, lora_A_q, lora_B_q,
                        b_pre, b_post, b_res, a_pre, a_post, a_res, norm_w);
    k_cvtW<<<dim3((DD*DATTNc+255)/256,32),256>>>(W_pre, wpreh_p, wprel_p, DD, DATTNc, DD, DATTNc);
    k_cvtW<<<dim3((DD*DPGp+255)/256,32),256>>>(W_pg1, wpg1h_p, wpg1l_p, DD, DPGc, DD, DPGp);
    k_cvtW<<<dim3((DPGp*DD+255)/256,32),256>>>(W_pg2, wpg2h_p, wpg2l_p, DPGc, DD, DPGp, DD);
    k_cvt_vk <<<(Hc*DD*128+255)/256,256>>>(Wv, Wk);
    k_cvt_mid<<<(HEc*DD*64+255)/256,256>>>(alpha_up, beta_up, lora_A_k, lora_A_v);
    k_gtmma2<256,128,3,0,1,1><<<dim3(32,2,8),256>>>(hekvh_p, hekvl_p, wvkh_p, wvkl_p,
                                                    vk_p, (__nv_bfloat16*)0, (__nv_bfloat16*)0,
                                                    idcnt_p, idlist_p);
    k_gtmma2<256,512,0,0,4,1><<<dim3(32,8,32),256>>>(hekvh_p, hekvl_p, wpreh_p, wprel_p,
                                                     preh_p, (__nv_bfloat16*)0, (__nv_bfloat16*)0,
                                                     kvcnt_p, kvlist_p);
    k_gtmma2<256,64,1,0,4,1><<<dim3(32,1,32),256>>>(hekvh_p, hekvl_p, wmidh_p, wmidl_p,
                                                    mid_p, (__nv_bfloat16*)0, (__nv_bfloat16*)0,
                                                    kvcnt_p, kvlist_p);
    k_gtmma2<256,320,1,1,4,1><<<dim3(32,5,32),256>>>(heqh_p, heql_p, wpg1h_p, wpg1l_p,
                                                     (float*)0, pgmh_p, pgml_p,
                                                     qcnt_p, qlist_p);
    k_gtmma2<320,256,2,0,4,1><<<dim3(32,4,32),256>>>(pgmh_p, pgml_p, wpg2h_p, wpg2l_p,
                                                     posth_p, (__nv_bfloat16*)0, (__nv_bfloat16*)0,
                                                     qcnt_p, qlist_p);
    k_finish<<<dim3(BT,Hc),64>>>(alpha_down, beta_down, lora_B_k, lora_B_v);
    k_rec  <<<dim3(32,16),128>>>();
    k_result<<<256,256>>>(W_o);
    k_final <<<BT,256>>>(stream, (float*)d_out);
}